// round 4
// baseline (speedup 1.0000x reference)
#include <cuda_runtime.h>
#include <cuda_fp16.h>
#include <cstdint>

// ---------------- problem constants ----------------
#define BATCH  16384
#define NFEAT  16
#define MTOT   4844
#define KPAD   4864          // padded K (mult of 64); pad monomial = 1, pad W = 0
#define KSTAGE 64
#define NSTAGE 76            // KPAD / KSTAGE
#define OUTD   256
#define BM     128           // batch rows per CTA
#define NTHR   512
#define ESTRIDE 155          // E-table row stride in floats (odd word count -> conflict-free)
#define ROWB    144          // A/B smem row pitch in bytes (64 halves + 16B pad)

// SMEM layout (dynamic, bytes)
#define A_BUFSZ 18432                         // 128 rows x 144B
#define B_BUFSZ 36864                         // 256 rows x 144B
#define A_OFF   0                             // 2 buffers
#define B_OFF   (2 * A_BUFSZ)                 // 36864, 3 buffers
#define E_OFF   (B_OFF + 3 * B_BUFSZ)         // 147456
#define BIAS_OFF (E_OFF + BM * ESTRIDE * 4)   // 226816
#define SMEM_REQ (BIAS_OFF + OUTD * 4)        // 227840

// ---------------- device globals (no cudaMalloc allowed) ----------------
__device__ __align__(16) __half g_Wh[OUTD * KPAD];  // fp16 W, [N=256][KPAD]
__device__ uint32_t g_TBL[KPAD];     // monomial m -> e1 | (e2<<16) into E table
__device__ uint32_t g_PAIRT[136];    // pair rank -> a | (b<<8)

__device__ __forceinline__ int pair_rank(int a, int b) {
    return a * 16 - (a * (a - 1)) / 2 + (b - a);
}

// Merged prep: pair table + monomial unranking (validated R1) + W fp16 conversion.
// One launch -> 2 launches per replay -> ncu -s 5 lands on taylor_main.
__global__ void prep_all(const float* __restrict__ W) {
    int idx = blockIdx.x * blockDim.x + threadIdx.x;
    if (idx < 136) {
        int r = idx, a = 0;
        while (r >= 16 - a) { r -= 16 - a; a++; }
        g_PAIRT[idx] = (uint32_t)a | ((uint32_t)(a + r) << 8);
    }
    if (idx < KPAD) {
        int m = idx;
        uint32_t e1 = 0, e2 = 0;
        if (m < 16) {
            e1 = 1 + m; e2 = 0;
        } else if (m < 152) {
            e1 = 17 + (m - 16); e2 = 0;
        } else if (m < 968) {
            int r = m - 152, a = 0;
            while (true) { int k = 16 - a; int t2 = k * (k + 1) / 2; if (r < t2) break; r -= t2; a++; }
            int b = a;
            while (r >= 16 - b) { r -= 16 - b; b++; }
            int c = b + r;
            e1 = 1 + a; e2 = 17 + pair_rank(b, c);
        } else if (m < MTOT) {
            int r = m - 968, a = 0;
            while (true) { int k = 16 - a; int t3 = k * (k + 1) * (k + 2) / 6; if (r < t3) break; r -= t3; a++; }
            int b = a;
            while (true) { int k = 16 - b; int t2 = k * (k + 1) / 2; if (r < t2) break; r -= t2; b++; }
            int c = b;
            while (r >= 16 - c) { r -= 16 - c; c++; }
            int d = c + r;
            e1 = 17 + pair_rank(a, b); e2 = 17 + pair_rank(c, d);
        } else {
            e1 = 0; e2 = 0;   // pad: monomial 1*1, weight forced to 0
        }
        g_TBL[m] = e1 | (e2 << 16);
    }
    if (idx < OUTD * KPAD) {
        int n = idx / KPAD, k = idx - n * KPAD;
        float w = (k < MTOT) ? W[(size_t)n * MTOT + k] : 0.0f;
        g_Wh[idx] = __float2half_rn(w);
    }
}

// ---------------- PTX helpers (sm_80-level only) ----------------
__device__ __forceinline__ uint32_t smem_u32(const void* p) {
    uint32_t a;
    asm("{ .reg .u64 t; cvta.to.shared.u64 t, %1; cvt.u32.u64 %0, t; }" : "=r"(a) : "l"(p));
    return a;
}
__device__ __forceinline__ void cp_async16(uint32_t dst, const void* src) {
    asm volatile("cp.async.cg.shared.global [%0], [%1], 16;" :: "r"(dst), "l"(src) : "memory");
}
__device__ __forceinline__ void ldsm_x4(uint32_t (&r)[4], uint32_t addr) {
    asm volatile("ldmatrix.sync.aligned.m8n8.x4.shared.b16 {%0,%1,%2,%3}, [%4];"
                 : "=r"(r[0]), "=r"(r[1]), "=r"(r[2]), "=r"(r[3]) : "r"(addr));
}
__device__ __forceinline__ void mma16816(float (&c)[4], const uint32_t (&a)[4],
                                         uint32_t b0, uint32_t b1) {
    asm volatile(
        "mma.sync.aligned.m16n8k16.row.col.f32.f16.f16.f32 "
        "{%0,%1,%2,%3}, {%4,%5,%6,%7}, {%8,%9}, {%0,%1,%2,%3};"
        : "+f"(c[0]), "+f"(c[1]), "+f"(c[2]), "+f"(c[3])
        : "r"(a[0]), "r"(a[1]), "r"(a[2]), "r"(a[3]), "r"(b0), "r"(b1));
}

// ---------------- main fused kernel ----------------
// 128 CTAs x 512 threads; CTA tile M=128 x N=256, K staged by 64.
// 16 warps 4x4: warp (wm,wn) owns rows wm*32..+32, cols wn*64..+64.
// A generated into registers during MMA of prior stage, STS'd at stage top.
// B triple-buffered via cp.async.
__global__ void __launch_bounds__(NTHR, 1) taylor_main(
    const float* __restrict__ x,
    const float* __restrict__ bias,
    float* __restrict__ out)
{
    extern __shared__ char smem[];
    const uint32_t sbase = smem_u32(smem);
    float* E    = (float*)(smem + E_OFF);
    float* Bias = (float*)(smem + BIAS_OFF);

    const int tid  = threadIdx.x;
    const int wid  = tid >> 5;
    const int lane = tid & 31;
    const int b0   = blockIdx.x * BM;
    const int wm   = wid & 3;
    const int wn   = wid >> 2;

    // ---- prologue: tanh + pairwise products into E ----
    #pragma unroll
    for (int i = 0; i < (BM * NFEAT) / NTHR; ++i) {
        int q = tid + i * NTHR;
        int row = q >> 4, f = q & 15;
        E[row * ESTRIDE + 1 + f] = tanhf(x[(size_t)(b0 + row) * NFEAT + f]);
    }
    if (tid < BM)   E[tid * ESTRIDE] = 1.0f;
    if (tid < OUTD) Bias[tid] = bias[tid];
    __syncthreads();
    #pragma unroll
    for (int i = 0; i < (136 * BM) / NTHR; ++i) {
        int q = tid + i * NTHR;
        int row = q & 127, p = q >> 7;
        uint32_t pr = g_PAIRT[p];
        E[row * ESTRIDE + 17 + p] =
            E[row * ESTRIDE + 1 + (pr & 255)] * E[row * ESTRIDE + 1 + ((pr >> 8) & 255)];
    }
    __syncthreads();

    // per-thread gen assignment: row = tid & 127, k-block of 16 = tid >> 7
    const int grow = tid & 127;
    const int gkb  = (tid >> 7) << 4;
    const float* Er = E + grow * ESTRIDE;
    uint32_t h[8];   // 16 generated halves, carried across stage boundary

    #define GENC(s_) do {                                                          \
        const int mb = (s_) * KSTAGE + gkb;                                        \
        _Pragma("unroll")                                                          \
        for (int q = 0; q < 8; ++q) {                                              \
            uint32_t t0 = __ldg(&g_TBL[mb + 2 * q]);                               \
            uint32_t t1 = __ldg(&g_TBL[mb + 2 * q + 1]);                           \
            float v0 = Er[t0 & 0xffff] * Er[t0 >> 16];                             \
            float v1 = Er[t1 & 0xffff] * Er[t1 >> 16];                             \
            asm("cvt.rn.f16x2.f32 %0, %1, %2;" : "=r"(h[q]) : "f"(v1), "f"(v0));   \
        }                                                                          \
    } while (0)

    #define STSA(s_) do {                                                          \
        uint32_t ad = sbase + A_OFF + (((s_) & 1) * A_BUFSZ) + grow * ROWB + gkb * 2; \
        asm volatile("st.shared.v4.b32 [%0], {%1,%2,%3,%4};"                       \
                     :: "r"(ad), "r"(h[0]), "r"(h[1]), "r"(h[2]), "r"(h[3]) : "memory"); \
        asm volatile("st.shared.v4.b32 [%0], {%1,%2,%3,%4};"                       \
                     :: "r"(ad + 16), "r"(h[4]), "r"(h[5]), "r"(h[6]), "r"(h[7]) : "memory"); \
    } while (0)

    #define LOAD_B(s_, buf_) do {                                                  \
        _Pragma("unroll")                                                          \
        for (int i = 0; i < 4; ++i) {                                              \
            int c = tid + i * NTHR;                                                \
            int row = c >> 3, seg = c & 7;                                         \
            const __half* src = g_Wh + (size_t)row * KPAD + (s_) * KSTAGE + seg * 8; \
            cp_async16(sbase + B_OFF + (buf_) * B_BUFSZ + row * ROWB + seg * 16, src); \
        }                                                                          \
        asm volatile("cp.async.commit_group;" ::: "memory");                       \
    } while (0)

    // ---- prologue of pipeline ----
    GENC(0);
    LOAD_B(0, 0);
    LOAD_B(1, 1);

    float acc[2][8][4];
    #pragma unroll
    for (int i = 0; i < 2; ++i)
        #pragma unroll
        for (int j = 0; j < 8; ++j)
            #pragma unroll
            for (int q = 0; q < 4; ++q) acc[i][j][q] = 0.0f;

    // ldmatrix lane addressing (buffer offset added per stage)
    const uint32_t aRowAddr = sbase + A_OFF + (wm * 32 + (lane & 15)) * ROWB + (lane >> 4) * 16;
    const int bq = lane >> 3;
    const uint32_t bRowAddr = sbase + B_OFF + (wn * 64 + ((bq >> 1) << 3) + (lane & 7)) * ROWB + (bq & 1) * 16;

    int bbuf = 0;   // s % 3
    for (int s = 0; s < NSTAGE; ++s) {
        if (s == NSTAGE - 1)
            asm volatile("cp.async.wait_group 0;" ::: "memory");
        else
            asm volatile("cp.async.wait_group 1;" ::: "memory");
        __syncthreads();              // B(s) visible; MMA(s-1) done reading A(s-1), B(s-1)

        STSA(s);                      // publish A(s) (computed last stage)
        if (s + 2 < NSTAGE) {
            int nb = bbuf + 2; if (nb >= 3) nb -= 3;
            LOAD_B(s + 2, nb);        // buf read at s-1; safe after the barrier above
        }
        __syncthreads();              // A(s) visible

        if (s + 1 < NSTAGE) GENC(s + 1);   // LDS/FMUL overlaps HMMA across warps

        const uint32_t aB = aRowAddr + (s & 1) * A_BUFSZ;
        const uint32_t bB = bRowAddr + bbuf * B_BUFSZ;
        #pragma unroll
        for (int kf = 0; kf < 4; ++kf) {
            uint32_t a[2][4];
            ldsm_x4(a[0], aB + kf * 32);
            ldsm_x4(a[1], aB + kf * 32 + 16 * ROWB);
            #pragma unroll
            for (int nb2 = 0; nb2 < 4; ++nb2) {
                uint32_t b[4];
                ldsm_x4(b, bB + nb2 * 16 * ROWB + kf * 32);
                mma16816(acc[0][nb2 * 2 + 0], a[0], b[0], b[1]);
                mma16816(acc[0][nb2 * 2 + 1], a[0], b[2], b[3]);
                mma16816(acc[1][nb2 * 2 + 0], a[1], b[0], b[1]);
                mma16816(acc[1][nb2 * 2 + 1], a[1], b[2], b[3]);
            }
        }

        if (++bbuf == 3) bbuf = 0;
    }

    // ---- epilogue: bias + relu + store ----
    {
        const int rbase = b0 + wm * 32 + (lane >> 2);
        const int cbase = wn * 64 + (lane & 3) * 2;
        #pragma unroll
        for (int mf = 0; mf < 2; ++mf) {
            #pragma unroll
            for (int nf = 0; nf < 8; ++nf) {
                const int col = cbase + nf * 8;
                const float bz0 = Bias[col], bz1 = Bias[col + 1];
                const int r0 = rbase + mf * 16;
                float2 v0, v1;
                v0.x = fmaxf(acc[mf][nf][0] + bz0, 0.0f);
                v0.y = fmaxf(acc[mf][nf][1] + bz1, 0.0f);
                v1.x = fmaxf(acc[mf][nf][2] + bz0, 0.0f);
                v1.y = fmaxf(acc[mf][nf][3] + bz1, 0.0f);
                *reinterpret_cast<float2*>(out + (size_t)r0 * OUTD + col)       = v0;
                *reinterpret_cast<float2*>(out + (size_t)(r0 + 8) * OUTD + col) = v1;
            }
        }
    }
    #undef GENC
    #undef STSA
    #undef LOAD_B
}

// ---------------- launch ----------------
extern "C" void kernel_launch(void* const* d_in, const int* in_sizes, int n_in,
                              void* d_out, int out_size) {
    const float* x = (const float*)d_in[0];   // [16384, 16, 1]
    const float* W = (const float*)d_in[1];   // [256, 4844]
    const float* b = (const float*)d_in[2];   // [256, 1]
    float* out = (float*)d_out;               // [16384, 256, 1]

    cudaFuncSetAttribute(taylor_main, cudaFuncAttributeMaxDynamicSharedMemorySize, SMEM_REQ);

    prep_all<<<(OUTD * KPAD + 255) / 256, 256>>>(W);
    taylor_main<<<BATCH / BM, NTHR, SMEM_REQ>>>(x, b, out);
}